// round 15
// baseline (speedup 1.0000x reference)
#include <cuda_runtime.h>
#include <cuda_bf16.h>
#include <mma.h>
#include <math.h>
#include <stdint.h>

using namespace nvcuda;

#define TEMP 0.0005f

// Shapes: B=32, C_MEL=80, C_TXT=512, C_ATT=80, T1=1600, T2=400
// Convs as flat GEMMs. K path N = 12800; Q path N = 51200.

// ---------------- fp32 scratch ----------------
#define F_SBK   0LL
#define F_SBQ   16384LL
#define F_TOTAL 18944LL
__device__ float g_f32[F_TOTAL];

// ---------------- bf16 scratch ----------------
#define H_WK1   0LL              // 1024*1536
#define H_WK2   1572864LL        // 80*1024
#define H_WQ1   1654784LL        // 160*256
#define H_WQ2   1695744LL        // 80*160
#define H_WQ3   1708544LL        // 80*96
#define H_WEND  1716224LL
#define H_IKEY  1716224LL        // 1536*12800
#define H_K1    21377024LL       // 1024*12800
#define H_IQ    34484224LL       // 256*51200
#define H_Q1    47591424LL       // 160*51200
#define H_Q2    55783424LL       // 96*51200 (rows 80..95 stay 0)
#define H_KOUT  60698624LL       // 80*12800
#define H_Q3    61722624LL       // 80*51200
#define H_TOTAL 65818624LL
__device__ __align__(16) __nv_bfloat16 g_bf16[H_TOTAL];

__device__ unsigned int g_mask_kind;

__global__ void detect_mask_kind(const unsigned int* __restrict__ mw)
{
    __shared__ unsigned int kinds;
    if (threadIdx.x == 0) kinds = 0u;
    __syncthreads();
    unsigned int local = 0u;
    for (int i = threadIdx.x; i < 3200; i += blockDim.x) {
        unsigned int v = mw[i];
        if (v == 0u) continue;
        else if (v == 1u) local |= 1u;
        else if (v == 0x3F800000u) local |= 2u;
        else local |= 4u;
    }
    atomicOr(&kinds, local);
    __syncthreads();
    if (threadIdx.x == 0) {
        unsigned int k = kinds;
        g_mask_kind = (k & 4u) ? 2u : ((k & 2u) ? 1u : 0u);
    }
}

// ---------------- speaker projection ----------------
__global__ __launch_bounds__(256) void spk_proj(
    const float* __restrict__ spk, const float* __restrict__ Wm,
    const float* __restrict__ bb, float* __restrict__ sb, int C)
{
    int b = blockIdx.x;
    int c = blockIdx.y * 256 + threadIdx.x;
    if (c >= C) return;
    const float* sp = spk + b * 512;
    const float4* wrow = (const float4*)(Wm + c * 512);
    const float4* sp4 = (const float4*)sp;
    float s = bb[c];
    #pragma unroll 4
    for (int j = 0; j < 128; j++) {
        float4 w = wrow[j], x = sp4[j];
        s += w.x * x.x + w.y * x.y + w.z * x.z + w.w * x.w;
    }
    sb[b * C + c] = s;
}

// ---------------- all weight conversions in one kernel ----------------
__global__ void convert_all(const float* __restrict__ Wk1, const float* __restrict__ Wk2,
                            const float* __restrict__ Wq1, const float* __restrict__ Wq2,
                            const float* __restrict__ Wq3, __nv_bfloat16* __restrict__ dst)
{
    for (long long i = blockIdx.x * (long long)blockDim.x + threadIdx.x; i < H_WEND;
         i += (long long)gridDim.x * blockDim.x) {
        const float* src; long long li; int K, Kp;
        if (i < H_WK2)      { src = Wk1; li = i - H_WK1; K = 1536; Kp = 1536; }
        else if (i < H_WQ1) { src = Wk2; li = i - H_WK2; K = 1024; Kp = 1024; }
        else if (i < H_WQ2) { src = Wq1; li = i - H_WQ1; K = 240;  Kp = 256; }
        else if (i < H_WQ3) { src = Wq2; li = i - H_WQ2; K = 160;  Kp = 160; }
        else                { src = Wq3; li = i - H_WQ3; K = 80;   Kp = 96; }
        long long m = li / Kp; int k = (int)(li - m * Kp);
        dst[i] = (k < K) ? __float2bfloat16(src[m * K + k]) : __float2bfloat16(0.f);
    }
}

// ---------------- im2col (k=3, pad=1) + speaker bias ----------------
__global__ void im2col_k(const float* __restrict__ x, const float* __restrict__ sb,
                         __nv_bfloat16* __restrict__ dst)
{
    const long long n = 1536LL * 12800;
    for (long long i = blockIdx.x * (long long)blockDim.x + threadIdx.x; i < n;
         i += (long long)gridDim.x * blockDim.x) {
        int col = (int)(i % 12800);
        int kk = (int)(i / 12800);
        int b = col / 400, t = col - b * 400;
        int ci = kk / 3, tap = kk - 3 * ci;
        int ts = t + tap - 1;
        float v = 0.f;
        if (ts >= 0 && ts < 400)
            v = x[((long long)b * 512 + ci) * 400 + ts] + sb[b * 512 + ci];
        dst[i] = __float2bfloat16(v);
    }
}

__global__ void im2col_q(const float* __restrict__ x, const float* __restrict__ sb,
                         __nv_bfloat16* __restrict__ dst)
{
    const long long n = 256LL * 51200;
    for (long long i = blockIdx.x * (long long)blockDim.x + threadIdx.x; i < n;
         i += (long long)gridDim.x * blockDim.x) {
        int col = (int)(i % 51200);
        int kk = (int)(i / 51200);
        int b = col / 1600, t = col - b * 1600;
        float v = 0.f;
        if (kk < 240) {
            int ci = kk / 3, tap = kk - 3 * ci;
            int ts = t + tap - 1;
            if (ts >= 0 && ts < 1600)
                v = x[((long long)b * 80 + ci) * 1600 + ts] + sb[b * 80 + ci];
        }
        dst[i] = __float2bfloat16(v);
    }
}

// ---------------- cp.async helpers ----------------
__device__ __forceinline__ void ldgsts16(unsigned int dst, const void* src, bool p) {
    asm volatile("cp.async.cg.shared.global [%0], [%1], 16, %2;\n"
                 :: "r"(dst), "l"(src), "r"(p ? 16 : 0));
}
__device__ __forceinline__ void cp_commit() { asm volatile("cp.async.commit_group;\n"); }
template<int N> __device__ __forceinline__ void cp_wait() {
    asm volatile("cp.async.wait_group %0;\n" :: "n"(N));
}

// ---------------- wide GEMM: 512 threads, 128m x 256n tile, BK=32 ----------------
// 3 smem slots, prefetch distance 2 (slot (i+2)%3 disjoint from active slot i%3).
#define WBM 128
#define WBN 256
#define WBK 32
#define WASTR 56    // A row stride elems (112B = 7 quads, coprime w/ 32)
#define WBSTR 264   // B row stride elems (528B = 33 quads, 33 ≡ 1 mod 32)
#define WASZ (WBM * WASTR * 2)        // 14336
#define WBSZ (WBK * WBSTR * 2)        // 16896
#define WSTG (WASZ + WBSZ)            // 31232
#define WGEMM_SMEM (3 * WSTG)         // 93696 (Cs 128*132*4 = 67584 fits)

template<bool RELU>
__global__ __launch_bounds__(512)
void gemm_wide(const __nv_bfloat16* __restrict__ A, int Kp,
               const __nv_bfloat16* __restrict__ Bm, long long Ntot,
               const float* __restrict__ bias, __nv_bfloat16* __restrict__ outp, int M)
{
    extern __shared__ char smc[];
    unsigned int sbase = (unsigned int)__cvta_generic_to_shared(smc);

    int tid = threadIdx.x;
    int wid = tid >> 5;
    int n0 = blockIdx.x * WBN;
    int m0 = blockIdx.y * WBM;

    int wm = (wid >> 3) * 64;      // 2 m-groups
    int wn = (wid & 7) * 32;       // 8 n-groups

    wmma::fragment<wmma::accumulator, 16, 16, 16, float> c[4][2];
    #pragma unroll
    for (int i = 0; i < 4; i++)
        #pragma unroll
        for (int j = 0; j < 2; j++) wmma::fill_fragment(c[i][j], 0.f);

    int nk = Kp / WBK;

    auto load_stage = [&](int slot, int kc) {
        unsigned int sa = sbase + slot * WSTG;
        // A: 128 rows x 32 elems = 512 x 16B chunks, 1 per thread
        {
            int row = tid >> 2;
            int c4 = tid & 3;
            bool pred = (m0 + row) < M;
            int rowc = pred ? (m0 + row) : (M - 1);
            ldgsts16(sa + row * (WASTR * 2) + c4 * 16,
                     A + (long long)rowc * Kp + kc + c4 * 8, pred);
        }
        // B: 32 rows x 32 chunks = 1024 x 16B chunks, 2/thread
        unsigned int sb2 = sa + WASZ;
        #pragma unroll
        for (int it = 0; it < 2; it++) {
            int cch = tid + it * 512;
            int row = cch >> 5;        // 0..31
            int c4 = cch & 31;         // 0..31
            ldgsts16(sb2 + row * (WBSTR * 2) + c4 * 16,
                     Bm + (long long)(kc + row) * Ntot + n0 + c4 * 8, true);
        }
    };

    // prologue: 2 stages in flight
    load_stage(0, 0); cp_commit();
    load_stage(1, WBK); cp_commit();

    for (int i = 0; i < nk; i++) {
        cp_wait<1>();              // stage i complete
        __syncthreads();
        int pf = i + 2;
        if (pf < nk) load_stage(pf % 3, pf * WBK);   // slot != i%3, != (i+1)%3
        cp_commit();

        const __nv_bfloat16* As = (const __nv_bfloat16*)(smc + (i % 3) * WSTG);
        const __nv_bfloat16* Bs = (const __nv_bfloat16*)(smc + (i % 3) * WSTG + WASZ);
        #pragma unroll
        for (int kk = 0; kk < WBK; kk += 16) {
            wmma::fragment<wmma::matrix_a, 16, 16, 16, __nv_bfloat16, wmma::row_major> a[4];
            wmma::fragment<wmma::matrix_b, 16, 16, 16, __nv_bfloat16, wmma::row_major> b[2];
            #pragma unroll
            for (int r = 0; r < 4; r++)
                wmma::load_matrix_sync(a[r], As + (wm + 16 * r) * WASTR + kk, WASTR);
            #pragma unroll
            for (int j = 0; j < 2; j++)
                wmma::load_matrix_sync(b[j], Bs + kk * WBSTR + wn + 16 * j, WBSTR);
            #pragma unroll
            for (int r = 0; r < 4; r++)
                #pragma unroll
                for (int j = 0; j < 2; j++)
                    wmma::mma_sync(c[r][j], a[r], b[j], c[r][j]);
        }
    }

    cp_wait<0>();
    __syncthreads();

    // epilogue in two 128-col halves through Cs[128][132]
    float* Cs = (float*)smc;
    #pragma unroll 1
    for (int half = 0; half < 2; half++) {
        if (((wid & 7) >> 2) == half) {
            int wnl = wn - half * 128;
            #pragma unroll
            for (int r = 0; r < 4; r++)
                #pragma unroll
                for (int j = 0; j < 2; j++)
                    wmma::store_matrix_sync(Cs + (wm + 16 * r) * 132 + wnl + 16 * j,
                                            c[r][j], 132, wmma::mem_row_major);
        }
        __syncthreads();
        int n = tid & 127;
        long long col = n0 + half * 128 + n;
        for (int m2 = tid >> 7; m2 < WBM; m2 += 4) {
            int mg = m0 + m2;
            if (mg < M) {
                float v = Cs[m2 * 132 + n] + bias[mg];
                if (RELU) v = fmaxf(v, 0.f);
                outp[(long long)mg * Ntot + col] = __float2bfloat16(v);
            }
        }
        __syncthreads();
    }
}

// ---------------- 4-stage pipelined bf16 WMMA GEMM (small convs) ----------------
#define GBM 128
#define GBN 128
#define GBK 32
#define ASTR 56
#define BSTR 152
#define ASZ (GBM * ASTR * 2)
#define BSZ (GBK * BSTR * 2)
#define STGB (ASZ + BSZ)
#define GEMM_SMEM (4 * STGB)

template<bool RELU>
__global__ __launch_bounds__(256)
void gemm_bf16(const __nv_bfloat16* __restrict__ A, int Kp,
               const __nv_bfloat16* __restrict__ Bm, long long Ntot,
               const float* __restrict__ bias, __nv_bfloat16* __restrict__ outp, int M)
{
    extern __shared__ char smc[];
    unsigned int sbase = (unsigned int)__cvta_generic_to_shared(smc);

    int tid = threadIdx.x;
    int wid = tid >> 5;
    int n0 = blockIdx.x * GBN;
    int m0 = blockIdx.y * GBM;

    int wm = (wid >> 2) * 64;
    int wn = (wid & 3) * 32;

    wmma::fragment<wmma::accumulator, 16, 16, 16, float> c[4][2];
    #pragma unroll
    for (int i = 0; i < 4; i++)
        #pragma unroll
        for (int j = 0; j < 2; j++) wmma::fill_fragment(c[i][j], 0.f);

    int nk = Kp / GBK;

    auto load_stage = [&](int slot, int kc) {
        unsigned int sa = sbase + slot * STGB;
        #pragma unroll
        for (int it = 0; it < 2; it++) {
            int cch = tid + it * 256;
            int row = cch >> 2;
            int coff = (cch & 3) << 3;
            bool pred = (m0 + row) < M;
            int rowc = pred ? (m0 + row) : (M - 1);
            ldgsts16(sa + row * (ASTR * 2) + ((cch & 3) << 4),
                     A + (long long)rowc * Kp + kc + coff, pred);
        }
        unsigned int sb2 = sa + ASZ;
        #pragma unroll
        for (int it = 0; it < 2; it++) {
            int cch = tid + it * 256;
            int row = cch >> 4;
            int coff = (cch & 15) << 3;
            ldgsts16(sb2 + row * (BSTR * 2) + ((cch & 15) << 4),
                     Bm + (long long)(kc + row) * Ntot + n0 + coff, true);
        }
    };

    load_stage(0, 0); cp_commit();
    load_stage(1, GBK); cp_commit();
    load_stage(2, 2 * GBK); cp_commit();

    for (int i = 0; i < nk; i++) {
        cp_wait<2>();
        __syncthreads();
        int pf = i + 3;
        if (pf < nk) load_stage(pf & 3, pf * GBK);
        cp_commit();

        const __nv_bfloat16* As = (const __nv_bfloat16*)(smc + (i & 3) * STGB);
        const __nv_bfloat16* Bs = (const __nv_bfloat16*)(smc + (i & 3) * STGB + ASZ);
        #pragma unroll
        for (int kk = 0; kk < GBK; kk += 16) {
            wmma::fragment<wmma::matrix_a, 16, 16, 16, __nv_bfloat16, wmma::row_major> a[4];
            wmma::fragment<wmma::matrix_b, 16, 16, 16, __nv_bfloat16, wmma::row_major> b[2];
            #pragma unroll
            for (int r = 0; r < 4; r++)
                wmma::load_matrix_sync(a[r], As + (wm + 16 * r) * ASTR + kk, ASTR);
            #pragma unroll
            for (int j = 0; j < 2; j++)
                wmma::load_matrix_sync(b[j], Bs + kk * BSTR + wn + 16 * j, BSTR);
            #pragma unroll
            for (int r = 0; r < 4; r++)
                #pragma unroll
                for (int j = 0; j < 2; j++)
                    wmma::mma_sync(c[r][j], a[r], b[j], c[r][j]);
        }
    }

    cp_wait<0>();
    __syncthreads();

    float* Cs = (float*)smc;
    #pragma unroll
    for (int r = 0; r < 4; r++)
        #pragma unroll
        for (int j = 0; j < 2; j++)
            wmma::store_matrix_sync(Cs + (wm + 16 * r) * 132 + wn + 16 * j,
                                    c[r][j], 132, wmma::mem_row_major);
    __syncthreads();

    int n = tid & 127;
    long long col = n0 + n;
    for (int m2 = tid >> 7; m2 < GBM; m2 += 2) {
        int mg = m0 + m2;
        if (mg >= M) break;
        float v = Cs[m2 * 132 + n] + bias[mg];
        if (RELU) v = fmaxf(v, 0.f);
        outp[(long long)mg * Ntot + col] = __float2bfloat16(v);
    }
}

// ---------------- fused attention with HMMA qk (512 threads) ----------------
__device__ __forceinline__ float warpMax(float v) {
    #pragma unroll
    for (int o = 16; o > 0; o >>= 1) v = fmaxf(v, __shfl_xor_sync(0xffffffffu, v, o));
    return v;
}
__device__ __forceinline__ float warpSum(float v) {
    #pragma unroll
    for (int o = 16; o > 0; o >>= 1) v += __shfl_xor_sync(0xffffffffu, v, o);
    return v;
}

#define AT1 64
#define KSLD 408
#define A_KSH_B   (96 * KSLD * 2)
#define A_SSH_B   (64 * KSLD * 4)
#define A_QSH_B   (64 * 96 * 2)
#define ATTN_SMEM (A_KSH_B + A_SSH_B + A_QSH_B + KSLD * 4 + 64 * 4)

__global__ __launch_bounds__(512) void attn_wmma(
    const __nv_bfloat16* __restrict__ qf,   // [80][51200]
    const __nv_bfloat16* __restrict__ kf,   // [80][12800]
    const float* __restrict__ prior, const void* __restrict__ maskp,
    float* __restrict__ attn_out, float* __restrict__ logprob_out)
{
    extern __shared__ char sm[];
    __nv_bfloat16* ksh = (__nv_bfloat16*)sm;
    float* Ssh = (float*)(sm + A_KSH_B);
    __nv_bfloat16* qsh = (__nv_bfloat16*)(sm + A_KSH_B + A_SSH_B);
    float* k2sh = (float*)(sm + A_KSH_B + A_SSH_B + A_QSH_B);
    float* q2sh = k2sh + KSLD;
    __shared__ unsigned char msh[400];

    int b = blockIdx.y;
    int t1_0 = blockIdx.x * AT1;
    int tid = threadIdx.x;
    int wid = tid >> 5;
    int lane = tid & 31;

    {
        unsigned int kind = g_mask_kind;
        if (kind == 0u) {
            const int* mi = (const int*)maskp;
            for (int s = tid; s < 400; s += 512) msh[s] = (mi[b * 400 + s] != 0);
        } else if (kind == 1u) {
            const float* mf = (const float*)maskp;
            for (int s = tid; s < 400; s += 512) msh[s] = (mf[b * 400 + s] != 0.f);
        } else {
            const unsigned char* mu = (const unsigned char*)maskp;
            for (int s = tid; s < 400; s += 512) msh[s] = (mu[b * 400 + s] != 0);
        }
    }

    {
        uint4 z = {0, 0, 0, 0};
        for (int idx = tid; idx < 96 + 16 * 51; idx += 512) {
            int row, c4;
            if (idx < 96) { row = idx; c4 = 50; }
            else { int j = idx - 96; row = 80 + j / 51; c4 = j % 51; }
            *(uint4*)(ksh + row * KSLD + c4 * 8) = z;
        }
    }
    for (int idx = tid; idx < 80 * 50; idx += 512) {
        int row = idx / 50, c4 = idx % 50;
        *(uint4*)(ksh + row * KSLD + c4 * 8) =
            *(const uint4*)(kf + (long long)row * 12800 + b * 400 + c4 * 8);
    }
    for (int idx = tid; idx < 96 * 64; idx += 512) {
        int c = idx >> 6, r = idx & 63;
        __nv_bfloat16 v = __float2bfloat16(0.f);
        if (c < 80) v = qf[(long long)c * 51200 + b * 1600 + t1_0 + r];
        qsh[r * 96 + c] = v;
    }
    __syncthreads();

    {
        int r = tid >> 3, part = tid & 7;
        float s = 0.f;
        int c0 = part * 10;
        for (int c = c0; c < c0 + 10; c++) {
            float v = __bfloat162float(qsh[r * 96 + c]);
            s += v * v;
        }
        s += __shfl_xor_sync(0xffffffffu, s, 1);
        s += __shfl_xor_sync(0xffffffffu, s, 2);
        s += __shfl_xor_sync(0xffffffffu, s, 4);
        if (part == 0) q2sh[r] = s;
    }
    for (int t2 = tid; t2 < KSLD; t2 += 512) {
        float s = 0.f;
        if (t2 < 400)
            for (int c = 0; c < 80; c++) {
                float v = __bfloat162float(ksh[c * KSLD + t2]);
                s += v * v;
            }
        k2sh[t2] = s;
    }

    {
        int wr = wid >> 3;
        int wc = wid & 7;
        wmma::fragment<wmma::accumulator, 16, 16, 16, float> acc[2][4];
        #pragma unroll
        for (int r = 0; r < 2; r++)
            #pragma unroll
            for (int j = 0; j < 4; j++) wmma::fill_fragment(acc[r][j], 0.f);

        for (int kk = 0; kk < 96; kk += 16) {
            wmma::fragment<wmma::matrix_a, 16, 16, 16, __nv_bfloat16, wmma::row_major> a[2];
            wmma::load_matrix_sync(a[0], qsh + (wr * 32) * 96 + kk, 96);
            wmma::load_matrix_sync(a[1], qsh + (wr * 32 + 16) * 96 + kk, 96);
            int ji = 0;
            for (int j = wc; j < 25; j += 8, ji++) {
                wmma::fragment<wmma::matrix_b, 16, 16, 16, __nv_bfloat16, wmma::row_major> bfrag;
                wmma::load_matrix_sync(bfrag, ksh + kk * KSLD + j * 16, KSLD);
                wmma::mma_sync(acc[0][ji], a[0], bfrag, acc[0][ji]);
                wmma::mma_sync(acc[1][ji], a[1], bfrag, acc[1][ji]);
            }
        }
        int ji = 0;
        for (int j = wc; j < 25; j += 8, ji++) {
            wmma::store_matrix_sync(Ssh + (wr * 32) * KSLD + j * 16, acc[0][ji],
                                    KSLD, wmma::mem_row_major);
            wmma::store_matrix_sync(Ssh + (wr * 32 + 16) * KSLD + j * 16, acc[1][ji],
                                    KSLD, wmma::mem_row_major);
        }
    }
    __syncthreads();

    for (int rr = 0; rr < 4; rr++) {
        int r = wid * 4 + rr;
        int t1 = t1_0 + r;
        float q2v = q2sh[r];
        float sc[13];
        float m = -INFINITY;
        #pragma unroll
        for (int i = 0; i < 13; i++) {
            int s = i * 32 + lane;
            sc[i] = (s < 400) ? (-TEMP * (q2v + k2sh[s] - 2.f * Ssh[r * KSLD + s]))
                              : -INFINITY;
            m = fmaxf(m, sc[i]);
        }
        m = warpMax(m);
        float sum = 0.f;
        #pragma unroll
        for (int i = 0; i < 13; i++) sum += __expf(sc[i] - m);
        sum = warpSum(sum);
        float lse = m + __logf(sum);

        long long base = ((long long)b * 1600 + t1) * 400;
        float xm[13];
        float m2 = -INFINITY;
        #pragma unroll
        for (int i = 0; i < 13; i++) {
            int s = i * 32 + lane;
            if (s < 400) {
                float lp = sc[i] - lse + __logf(prior[base + s] + 1e-8f);
                logprob_out[base + s] = lp;
                xm[i] = msh[s] ? -INFINITY : lp;
            } else xm[i] = -INFINITY;
            m2 = fmaxf(m2, xm[i]);
        }
        m2 = warpMax(m2);
        float s2 = 0.f;
        #pragma unroll
        for (int i = 0; i < 13; i++) {
            xm[i] = (xm[i] == -INFINITY) ? 0.f : __expf(xm[i] - m2);
            s2 += xm[i];
        }
        s2 = warpSum(s2);
        float inv = 1.f / s2;
        #pragma unroll
        for (int i = 0; i < 13; i++) {
            int s = i * 32 + lane;
            if (s < 400) attn_out[base + s] = xm[i] * inv;
        }
    }
}

// ---------------- launch ----------------
extern "C" void kernel_launch(void* const* d_in, const int* in_sizes, int n_in,
                              void* d_out, int out_size)
{
    const float* queries = (const float*)d_in[0];
    const float* keys    = (const float*)d_in[1];
    const void*  mask    = (const void*)d_in[2];
    const float* prior   = (const float*)d_in[3];
    const float* spk     = (const float*)d_in[4];
    const float* Wk1 = (const float*)d_in[5];
    const float* bk1 = (const float*)d_in[6];
    const float* Wk2 = (const float*)d_in[7];
    const float* bk2 = (const float*)d_in[8];
    const float* Wq1 = (const float*)d_in[9];
    const float* bq1 = (const float*)d_in[10];
    const float* Wq2 = (const float*)d_in[11];
    const float* bq2 = (const float*)d_in[12];
    const float* Wq3 = (const float*)d_in[13];
    const float* bq3 = (const float*)d_in[14];
    const float* Wks = (const float*)d_in[15];
    const float* bks = (const float*)d_in[16];
    const float* Wqs = (const float*)d_in[17];
    const float* bqs = (const float*)d_in[18];

    float* out = (float*)d_out;
    float* attn_out = out;
    float* logprob_out = out + (long long)32 * 1600 * 400;

    float* f32 = nullptr;
    __nv_bfloat16* h = nullptr;
    cudaGetSymbolAddress((void**)&f32, g_f32);
    cudaGetSymbolAddress((void**)&h, g_bf16);

    float* sbk = f32 + F_SBK;
    float* sbq = f32 + F_SBQ;

    __nv_bfloat16* Wk1b  = h + H_WK1;
    __nv_bfloat16* Wk2b  = h + H_WK2;
    __nv_bfloat16* Wq1b  = h + H_WQ1;
    __nv_bfloat16* Wq2b  = h + H_WQ2;
    __nv_bfloat16* Wq3b  = h + H_WQ3;
    __nv_bfloat16* ikey  = h + H_IKEY;
    __nv_bfloat16* k1b   = h + H_K1;
    __nv_bfloat16* iq    = h + H_IQ;
    __nv_bfloat16* q1b   = h + H_Q1;
    __nv_bfloat16* q2b   = h + H_Q2;
    __nv_bfloat16* kflat = h + H_KOUT;
    __nv_bfloat16* qflat = h + H_Q3;

    cudaFuncSetAttribute((const void*)&gemm_wide<true>,
                         cudaFuncAttributeMaxDynamicSharedMemorySize, WGEMM_SMEM);
    cudaFuncSetAttribute((const void*)&gemm_bf16<true>,
                         cudaFuncAttributeMaxDynamicSharedMemorySize, GEMM_SMEM);
    cudaFuncSetAttribute((const void*)&gemm_bf16<false>,
                         cudaFuncAttributeMaxDynamicSharedMemorySize, GEMM_SMEM);
    cudaFuncSetAttribute(attn_wmma, cudaFuncAttributeMaxDynamicSharedMemorySize, ATTN_SMEM);

    // index 3 = ncu capture slot -> wide k1 GEMM
    spk_proj<<<dim3(32, 2), 256>>>(spk, Wks, bks, sbk, 512);            // 0
    convert_all<<<2048, 256>>>(Wk1, Wk2, Wq1, Wq2, Wq3, h);             // 1
    im2col_k<<<8192, 256>>>(keys, sbk, ikey);                           // 2
    // K conv1: [1024 x 12800 x 1536] + relu
    gemm_wide<true><<<dim3(50, 8), 512, WGEMM_SMEM>>>(Wk1b, 1536, ikey, 12800LL, bk1, k1b, 1024); // 3

    detect_mask_kind<<<1, 256>>>((const unsigned int*)mask);            // 4
    spk_proj<<<dim3(32, 1), 256>>>(spk, Wqs, bqs, sbq, 80);             // 5
    im2col_q<<<8192, 256>>>(queries, sbq, iq);                          // 6

    // K conv2: [80 x 12800 x 1024]
    gemm_bf16<false><<<dim3(100, 1), 256, GEMM_SMEM>>>(Wk2b, 1024, k1b, 12800LL, bk2, kflat, 80);

    // Q path: q1 on wide kernel, q2/q3 on small kernel
    gemm_wide<true><<<dim3(200, 2), 512, WGEMM_SMEM>>>(Wq1b, 256, iq, 51200LL, bq1, q1b, 160);
    gemm_bf16<true><<<dim3(400, 1), 256, GEMM_SMEM>>>(Wq2b, 160, q1b, 51200LL, bq2, q2b, 80);
    gemm_bf16<false><<<dim3(400, 1), 256, GEMM_SMEM>>>(Wq3b, 96, q2b, 51200LL, bq3, qflat, 80);

    // fused attention
    attn_wmma<<<dim3(25, 32), 512, ATTN_SMEM>>>(qflat, kflat, prior, mask, attn_out, logprob_out);
}